// round 8
// baseline (speedup 1.0000x reference)
#include <cuda_runtime.h>
#include <cuda_bf16.h>

#define NF 5
#define GG 32
#define STRIDE_V 520
#define TPB 256

// XLA folds x / 0.01f into x * fl(1/fl(0.01f)) == x * 100.0f exactly.
#define INV_V 100.0f

__device__ __forceinline__ float pick4(float a, float b, float c, float d, int s) {
    float lo = (s & 1) ? b : a;
    float hi = (s & 1) ? d : c;
    return (s & 2) ? hi : lo;
}

__global__ __launch_bounds__(TPB, 4) void hashgrid_kernel(
    const float* __restrict__ x,
    const float* __restrict__ feat,
    const int*   __restrict__ btab,
    float* __restrict__ out,
    int n)
{
    __shared__ __align__(16) float s_feats[TPB * NF];
    __shared__ __align__(16) float s_dfx[TPB * NF * 3];
    __shared__ __align__(16) float s_mask[TPB];

    const int tid = threadIdx.x;
    const int blk = blockIdx.x;
    const int i = blk * TPB + tid;
    int rem = n - blk * TPB;
    if (rem > TPB) rem = TPB;

    float S[NF]  = {0.f, 0.f, 0.f, 0.f, 0.f};
    float Sx[NF] = {0.f, 0.f, 0.f, 0.f, 0.f};
    float Sy[NF] = {0.f, 0.f, 0.f, 0.f, 0.f};
    float Sz[NF] = {0.f, 0.f, 0.f, 0.f, 0.f};
    float m = 0.0f;

    if (i < n) {
        float ux = x[3 * i + 0] * INV_V;
        float uy = x[3 * i + 1] * INV_V;
        float uz = x[3 * i + 2] * INV_V;

        float fx = floorf(ux), fy = floorf(uy), fz = floorf(uz);
        int xi = (int)fx, yi = (int)fy, zi = (int)fz;
        float frx = ux - fx, fry = uy - fy, frz = uz - fz;

        // ---- block-table lookups with dedup ----
        int bx0 = xi >> 3, bx1 = (xi + 1) >> 3;
        int by0 = yi >> 3, by1 = (yi + 1) >> 3;
        int bz0 = zi >> 3, bz1 = (zi + 1) >> 3;
        bool px = (bx1 != bx0), py = (by1 != by0), pz = (bz1 != bz0);
        bool vx1 = (bx1 < GG), vy1 = (by1 < GG), vz1 = (bz1 < GG);
        int base = (bx0 * GG + by0) * GG + bz0;

        int t000 = __ldg(btab + base);
        int t100 = t000; if (px) t100 = vx1 ? __ldg(btab + base + GG * GG) : -1;
        int t010 = t000; if (py) t010 = vy1 ? __ldg(btab + base + GG) : -1;
        int t001 = t000; if (pz) t001 = vz1 ? __ldg(btab + base + 1) : -1;
        int t110;
        if (px && py)      t110 = (vx1 && vy1) ? __ldg(btab + base + GG * GG + GG) : -1;
        else if (px)       t110 = t100;
        else               t110 = t010;
        int t101;
        if (px && pz)      t101 = (vx1 && vz1) ? __ldg(btab + base + GG * GG + 1) : -1;
        else if (px)       t101 = t100;
        else               t101 = t001;
        int t011;
        if (py && pz)      t011 = (vy1 && vz1) ? __ldg(btab + base + GG + 1) : -1;
        else if (py)       t011 = t010;
        else               t011 = t001;
        int t111;
        if (!pz)           t111 = t110;
        else if (!py)      t111 = t101;
        else if (!px)      t111 = t011;
        else               t111 = (vx1 && vy1 && vz1) ? __ldg(btab + base + GG * GG + GG + 1) : -1;

        int tb[8] = {t000, t001, t010, t011, t100, t101, t110, t111};

        bool ok = true;
        int foff[8];
        int lx0 = xi & 7, lx1 = (xi + 1) & 7;
        int ly0 = yi & 7, ly1 = (yi + 1) & 7;
        int lz0 = zi & 7, lz1 = (zi + 1) & 7;
        #pragma unroll
        for (int c = 0; c < 8; c++) {
            int b = tb[c];
            ok = ok && (b >= 0);
            int bs = b < 0 ? 0 : b;
            int lx = (c & 4) ? lx1 : lx0;
            int ly = (c & 2) ? ly1 : ly0;
            int lz = (c & 1) ? lz1 : lz0;
            foff[c] = bs * (STRIDE_V * NF) + ((lx * 8 + ly) * 8 + lz) * NF;
        }
        m = ok ? 1.0f : 0.0f;

        float wx1v = frx, wx0v = 1.0f - frx;
        float wy1v = fry, wy0v = 1.0f - fry;

        // ---- gather + reduce: 2 fused z-pairs per iteration ----
        // z-pair (c, c+1) is contiguous (fo1 == fo0+5) 7/8 of the time ->
        // 3 shared float4 loads cover both corners (plus rare predicated extras).
        #pragma unroll 1
        for (int h = 0; h < 2; h++) {
            int fo0a = foff[h * 4 + 0], fo1a = foff[h * 4 + 1];
            int fo0b = foff[h * 4 + 2], fo1b = foff[h * 4 + 3];
            bool fua = (fo1a == fo0a + 5);
            bool fub = (fo1b == fo0b + 5);
            int sha = fo0a & 3, shb = fo0b & 3;

            const float4* pa = reinterpret_cast<const float4*>(feat) + (fo0a >> 2);
            const float4* pb = reinterpret_cast<const float4*>(feat) + (fo0b >> 2);
            float4 Ca0 = __ldg(pa), Ca1 = __ldg(pa + 1), Ca2 = __ldg(pa + 2);
            float4 Cb0 = __ldg(pb), Cb1 = __ldg(pb + 1), Cb2 = __ldg(pb + 2);

            float ea12 = 0.0f, eb12 = 0.0f;
            float4 Da0, Da1, Db0, Db1;
            int sh1a = 0, sh1b = 0;
            if (fua) {
                if (sha == 3) ea12 = __ldg(reinterpret_cast<const float*>(pa) + 12);
            } else {
                const float4* qa = reinterpret_cast<const float4*>(feat) + (fo1a >> 2);
                Da0 = __ldg(qa); Da1 = __ldg(qa + 1);
                sh1a = fo1a & 3;
            }
            if (fub) {
                if (shb == 3) eb12 = __ldg(reinterpret_cast<const float*>(pb) + 12);
            } else {
                const float4* qb = reinterpret_cast<const float4*>(feat) + (fo1b >> 2);
                Db0 = __ldg(qb); Db1 = __ldg(qb + 1);
                sh1b = fo1b & 3;
            }

            #pragma unroll
            for (int q = 0; q < 2; q++) {
                float e[13];
                if (q == 0) {
                    e[0]=Ca0.x; e[1]=Ca0.y; e[2]=Ca0.z; e[3]=Ca0.w;
                    e[4]=Ca1.x; e[5]=Ca1.y; e[6]=Ca1.z; e[7]=Ca1.w;
                    e[8]=Ca2.x; e[9]=Ca2.y; e[10]=Ca2.z; e[11]=Ca2.w;
                    e[12]=ea12;
                } else {
                    e[0]=Cb0.x; e[1]=Cb0.y; e[2]=Cb0.z; e[3]=Cb0.w;
                    e[4]=Cb1.x; e[5]=Cb1.y; e[6]=Cb1.z; e[7]=Cb1.w;
                    e[8]=Cb2.x; e[9]=Cb2.y; e[10]=Cb2.z; e[11]=Cb2.w;
                    e[12]=eb12;
                }
                bool fu = (q == 0) ? fua : fub;
                int  sh = (q == 0) ? sha : shb;

                float v0[NF], v1[NF];
                #pragma unroll
                for (int f = 0; f < NF; f++)
                    v0[f] = pick4(e[f], e[f+1], e[f+2], e[f+3], sh);

                if (fu) {
                    #pragma unroll
                    for (int f = 0; f < NF; f++)
                        v1[f] = pick4(e[f+5], e[f+6], e[f+7], e[f+8], sh);
                } else {
                    float d[8];
                    if (q == 0) {
                        d[0]=Da0.x; d[1]=Da0.y; d[2]=Da0.z; d[3]=Da0.w;
                        d[4]=Da1.x; d[5]=Da1.y; d[6]=Da1.z; d[7]=Da1.w;
                    } else {
                        d[0]=Db0.x; d[1]=Db0.y; d[2]=Db0.z; d[3]=Db0.w;
                        d[4]=Db1.x; d[5]=Db1.y; d[6]=Db1.z; d[7]=Db1.w;
                    }
                    int s1 = (q == 0) ? sh1a : sh1b;
                    #pragma unroll
                    for (int f = 0; f < NF; f++)
                        v1[f] = pick4(d[f], d[f+1], d[f+2], d[f+3], s1);
                }

                // corner c = h*4 + 2q : cx = h, cy = q
                float wx = h ? wx1v : wx0v;
                float wy = q ? wy1v : wy0v;
                float wxy  = wx * wy;
                float sxwy = h ? wy : -wy;   // sx * wy
                float wxsy = q ? wx : -wx;   // wx * sy

                #pragma unroll
                for (int f = 0; f < NF; f++) {
                    float tz = v1[f] - v0[f];
                    float t  = fmaf(tz, frz, v0[f]);   // lerp over z
                    S[f]  = fmaf(wxy,  t,  S[f]);
                    Sx[f] = fmaf(sxwy, t,  Sx[f]);
                    Sy[f] = fmaf(wxsy, t,  Sy[f]);
                    Sz[f] = fmaf(wxy,  tz, Sz[f]);
                }
            }
        }
    }

    // ---- stage per-thread outputs in smem ----
    #pragma unroll
    for (int f = 0; f < NF; f++) s_feats[tid * NF + f] = S[f] * m;
    float md = m * INV_V;
    #pragma unroll
    for (int f = 0; f < NF; f++) {
        s_dfx[tid * (NF * 3) + f * 3 + 0] = Sx[f] * md;
        s_dfx[tid * (NF * 3) + f * 3 + 1] = Sy[f] * md;
        s_dfx[tid * (NF * 3) + f * 3 + 2] = Sz[f] * md;
    }
    s_mask[tid] = m;
    __syncthreads();

    // ---- coalesced float4 stores of this block's three output segments ----
    {
        int cnt = rem * NF;
        float* g = out + (size_t)blk * TPB * NF;
        const float4* s4 = (const float4*)s_feats;
        float4* g4 = (float4*)g;
        int n4 = cnt >> 2;
        for (int idx = tid; idx < n4; idx += TPB) g4[idx] = s4[idx];
        for (int idx = (n4 << 2) + tid; idx < cnt; idx += TPB) g[idx] = s_feats[idx];
    }
    {
        int cnt = rem * NF * 3;
        float* g = out + (size_t)n * NF + (size_t)blk * TPB * NF * 3;
        const float4* s4 = (const float4*)s_dfx;
        float4* g4 = (float4*)g;
        int n4 = cnt >> 2;
        for (int idx = tid; idx < n4; idx += TPB) g4[idx] = s4[idx];
        for (int idx = (n4 << 2) + tid; idx < cnt; idx += TPB) g[idx] = s_dfx[idx];
    }
    {
        int cnt = rem;
        float* g = out + (size_t)n * NF * 4 + (size_t)blk * TPB;
        const float4* s4 = (const float4*)s_mask;
        float4* g4 = (float4*)g;
        int n4 = cnt >> 2;
        for (int idx = tid; idx < n4; idx += TPB) g4[idx] = s4[idx];
        for (int idx = (n4 << 2) + tid; idx < cnt; idx += TPB) g[idx] = s_mask[idx];
    }
}

extern "C" void kernel_launch(void* const* d_in, const int* in_sizes, int n_in,
                              void* d_out, int out_size)
{
    const float* x    = (const float*)d_in[0];
    const float* feat = (const float*)d_in[1];
    const int*   btab = (const int*)d_in[2];
    float* out = (float*)d_out;

    int n = in_sizes[0] / 3;
    int blocks = (n + TPB - 1) / TPB;
    hashgrid_kernel<<<blocks, TPB>>>(x, feat, btab, out, n);
}

// round 9
// speedup vs baseline: 2.0649x; 2.0649x over previous
#include <cuda_runtime.h>
#include <cuda_bf16.h>

#define NF 5
#define GG 32
#define STRIDE_V 520
#define TPB 256

// XLA folds x / 0.01f into x * fl(1/fl(0.01f)) == x * 100.0f exactly.
#define INV_V 100.0f

__global__ __launch_bounds__(TPB) void hashgrid_kernel(
    const float* __restrict__ x,
    const float* __restrict__ feat,
    const int*   __restrict__ btab,
    float* __restrict__ out,
    int n)
{
    __shared__ __align__(16) float s_feats[TPB * NF];
    __shared__ __align__(16) float s_dfx[TPB * NF * 3];
    __shared__ __align__(16) float s_mask[TPB];

    const int tid = threadIdx.x;
    const int blk = blockIdx.x;
    const int i = blk * TPB + tid;
    int rem = n - blk * TPB;
    if (rem > TPB) rem = TPB;

    float acc[NF] = {0.f, 0.f, 0.f, 0.f, 0.f};
    float accd[NF][3];
    #pragma unroll
    for (int f = 0; f < NF; f++) { accd[f][0] = 0.f; accd[f][1] = 0.f; accd[f][2] = 0.f; }
    float m = 0.0f;

    if (i < n) {
        float ux = x[3 * i + 0] * INV_V;
        float uy = x[3 * i + 1] * INV_V;
        float uz = x[3 * i + 2] * INV_V;

        float fx = floorf(ux), fy = floorf(uy), fz = floorf(uz);
        int xi = (int)fx, yi = (int)fy, zi = (int)fz;
        float frx = ux - fx, fry = uy - fy, frz = uz - fz;

        // ---- block-table lookups with dedup (corners share blocks unless on a face) ----
        int bx0 = xi >> 3, bx1 = (xi + 1) >> 3;
        int by0 = yi >> 3, by1 = (yi + 1) >> 3;
        int bz0 = zi >> 3, bz1 = (zi + 1) >> 3;
        bool px = (bx1 != bx0), py = (by1 != by0), pz = (bz1 != bz0);
        bool vx1 = (bx1 < GG), vy1 = (by1 < GG), vz1 = (bz1 < GG);
        int base = (bx0 * GG + by0) * GG + bz0;

        int t000 = __ldg(btab + base);
        int t100 = t000; if (px) t100 = vx1 ? __ldg(btab + base + GG * GG) : -1;
        int t010 = t000; if (py) t010 = vy1 ? __ldg(btab + base + GG) : -1;
        int t001 = t000; if (pz) t001 = vz1 ? __ldg(btab + base + 1) : -1;
        int t110;
        if (px && py)      t110 = (vx1 && vy1) ? __ldg(btab + base + GG * GG + GG) : -1;
        else if (px)       t110 = t100;
        else               t110 = t010;
        int t101;
        if (px && pz)      t101 = (vx1 && vz1) ? __ldg(btab + base + GG * GG + 1) : -1;
        else if (px)       t101 = t100;
        else               t101 = t001;
        int t011;
        if (py && pz)      t011 = (vy1 && vz1) ? __ldg(btab + base + GG + 1) : -1;
        else if (py)       t011 = t010;
        else               t011 = t001;
        int t111;
        if (!pz)           t111 = t110;
        else if (!py)      t111 = t101;
        else if (!px)      t111 = t011;
        else               t111 = (vx1 && vy1 && vz1) ? __ldg(btab + base + GG * GG + GG + 1) : -1;

        int tb[8] = {t000, t001, t010, t011, t100, t101, t110, t111};

        bool ok = true;
        int foff[8];
        int lx0 = xi & 7, lx1 = (xi + 1) & 7;
        int ly0 = yi & 7, ly1 = (yi + 1) & 7;
        int lz0 = zi & 7, lz1 = (zi + 1) & 7;
        #pragma unroll
        for (int c = 0; c < 8; c++) {
            int b = tb[c];
            ok = ok && (b >= 0);
            int bs = b < 0 ? 0 : b;
            int lx = (c & 4) ? lx1 : lx0;
            int ly = (c & 2) ? ly1 : ly0;
            int lz = (c & 1) ? lz1 : lz0;
            foff[c] = bs * (STRIDE_V * NF) + ((lx * 8 + ly) * 8 + lz) * NF;
        }
        m = ok ? 1.0f : 0.0f;

        // ~48% of points have a missing corner block: their gathers contribute
        // nothing (reference multiplies by mask). Skip them entirely —
        // predicated-off lanes generate no L1 wavefronts and no DRAM sectors.
        if (ok) {
            float wx1 = frx, wx0 = 1.0f - frx;
            float wy1 = fry, wy0 = 1.0f - fry;
            float wz1 = frz, wz0 = 1.0f - frz;

            // ---- gather: 2x LDG.128 per corner (20B span always inside 32B window) ----
            #pragma unroll
            for (int h = 0; h < 2; h++) {
                float4 A[4], B[4];
                int sh[4];
                #pragma unroll
                for (int q = 0; q < 4; q++) {
                    int fo = foff[h * 4 + q];
                    sh[q] = fo & 3;
                    const float4* p = reinterpret_cast<const float4*>(feat + (fo & ~3));
                    A[q] = __ldg(p);
                    B[q] = __ldg(p + 1);
                }
                #pragma unroll
                for (int q = 0; q < 4; q++) {
                    int c = h * 4 + q;
                    bool s1 = (sh[q] & 1) != 0;
                    bool s2 = (sh[q] & 2) != 0;
                    float e0 = A[q].x, e1 = A[q].y, e2 = A[q].z, e3 = A[q].w;
                    float e4 = B[q].x, e5 = B[q].y, e6 = B[q].z, e7 = B[q].w;
                    float v0 = s2 ? (s1 ? e3 : e2) : (s1 ? e1 : e0);
                    float v1 = s2 ? (s1 ? e4 : e3) : (s1 ? e2 : e1);
                    float v2 = s2 ? (s1 ? e5 : e4) : (s1 ? e3 : e2);
                    float v3 = s2 ? (s1 ? e6 : e5) : (s1 ? e4 : e3);
                    float v4 = s2 ? (s1 ? e7 : e6) : (s1 ? e5 : e4);

                    float wx = (c & 4) ? wx1 : wx0;
                    float wy = (c & 2) ? wy1 : wy0;
                    float wz = (c & 1) ? wz1 : wz0;
                    float sx = (c & 4) ? 1.0f : -1.0f;
                    float sy = (c & 2) ? 1.0f : -1.0f;
                    float sz = (c & 1) ? 1.0f : -1.0f;
                    float w   = wx * wy * wz;
                    float dwx = sx * wy * wz;
                    float dwy = wx * sy * wz;
                    float dwz = wx * wy * sz;

                    float vv[NF] = {v0, v1, v2, v3, v4};
                    #pragma unroll
                    for (int f = 0; f < NF; f++) {
                        float t = vv[f];
                        acc[f]     = fmaf(w,   t, acc[f]);
                        accd[f][0] = fmaf(dwx, t, accd[f][0]);
                        accd[f][1] = fmaf(dwy, t, accd[f][1]);
                        accd[f][2] = fmaf(dwz, t, accd[f][2]);
                    }
                }
            }
        }
    }

    // ---- stage per-thread outputs in smem ----
    #pragma unroll
    for (int f = 0; f < NF; f++) s_feats[tid * NF + f] = acc[f] * m;
    float md = m * INV_V;
    #pragma unroll
    for (int f = 0; f < NF; f++) {
        s_dfx[tid * (NF * 3) + f * 3 + 0] = accd[f][0] * md;
        s_dfx[tid * (NF * 3) + f * 3 + 1] = accd[f][1] * md;
        s_dfx[tid * (NF * 3) + f * 3 + 2] = accd[f][2] * md;
    }
    s_mask[tid] = m;
    __syncthreads();

    // ---- coalesced float4 stores of this block's three output segments ----
    {
        int cnt = rem * NF;
        float* g = out + (size_t)blk * TPB * NF;
        const float4* s4 = (const float4*)s_feats;
        float4* g4 = (float4*)g;
        int n4 = cnt >> 2;
        for (int idx = tid; idx < n4; idx += TPB) g4[idx] = s4[idx];
        for (int idx = (n4 << 2) + tid; idx < cnt; idx += TPB) g[idx] = s_feats[idx];
    }
    {
        int cnt = rem * NF * 3;
        float* g = out + (size_t)n * NF + (size_t)blk * TPB * NF * 3;
        const float4* s4 = (const float4*)s_dfx;
        float4* g4 = (float4*)g;
        int n4 = cnt >> 2;
        for (int idx = tid; idx < n4; idx += TPB) g4[idx] = s4[idx];
        for (int idx = (n4 << 2) + tid; idx < cnt; idx += TPB) g[idx] = s_dfx[idx];
    }
    {
        int cnt = rem;
        float* g = out + (size_t)n * NF * 4 + (size_t)blk * TPB;
        const float4* s4 = (const float4*)s_mask;
        float4* g4 = (float4*)g;
        int n4 = cnt >> 2;
        for (int idx = tid; idx < n4; idx += TPB) g4[idx] = s4[idx];
        for (int idx = (n4 << 2) + tid; idx < cnt; idx += TPB) g[idx] = s_mask[idx];
    }
}

extern "C" void kernel_launch(void* const* d_in, const int* in_sizes, int n_in,
                              void* d_out, int out_size)
{
    const float* x    = (const float*)d_in[0];
    const float* feat = (const float*)d_in[1];
    const int*   btab = (const int*)d_in[2];
    float* out = (float*)d_out;

    int n = in_sizes[0] / 3;
    int blocks = (n + TPB - 1) / TPB;
    hashgrid_kernel<<<blocks, TPB>>>(x, feat, btab, out, n);
}

// round 10
// speedup vs baseline: 2.0724x; 1.0036x over previous
#include <cuda_runtime.h>
#include <cuda_bf16.h>

#define NF 5
#define GG 32
#define STRIDE_V 520
#define TPB 256

// XLA folds x / 0.01f into x * fl(1/fl(0.01f)) == x * 100.0f exactly.
#define INV_V 100.0f

__global__ __launch_bounds__(TPB) void hashgrid_kernel(
    const float* __restrict__ x,
    const float* __restrict__ feat,
    const int*   __restrict__ btab,
    float* __restrict__ out,
    int n)
{
    __shared__ __align__(16) float s_feats[TPB * NF];
    __shared__ __align__(16) float s_dfx[TPB * NF * 3];
    __shared__ __align__(16) float s_mask[TPB];

    const int tid = threadIdx.x;
    const int blk = blockIdx.x;
    const int i = blk * TPB + tid;
    int rem = n - blk * TPB;
    if (rem > TPB) rem = TPB;

    float acc[NF] = {0.f, 0.f, 0.f, 0.f, 0.f};
    float accd[NF][3];
    #pragma unroll
    for (int f = 0; f < NF; f++) { accd[f][0] = 0.f; accd[f][1] = 0.f; accd[f][2] = 0.f; }
    float m = 0.0f;

    if (i < n) {
        // x is read exactly once -> evict-first, keep L2 for the feat table.
        float ux = __ldcs(x + 3 * i + 0) * INV_V;
        float uy = __ldcs(x + 3 * i + 1) * INV_V;
        float uz = __ldcs(x + 3 * i + 2) * INV_V;

        float fx = floorf(ux), fy = floorf(uy), fz = floorf(uz);
        int xi = (int)fx, yi = (int)fy, zi = (int)fz;
        float frx = ux - fx, fry = uy - fy, frz = uz - fz;

        // ---- block-table lookups with dedup (corners share blocks unless on a face) ----
        int bx0 = xi >> 3, bx1 = (xi + 1) >> 3;
        int by0 = yi >> 3, by1 = (yi + 1) >> 3;
        int bz0 = zi >> 3, bz1 = (zi + 1) >> 3;
        bool px = (bx1 != bx0), py = (by1 != by0), pz = (bz1 != bz0);
        bool vx1 = (bx1 < GG), vy1 = (by1 < GG), vz1 = (bz1 < GG);
        int base = (bx0 * GG + by0) * GG + bz0;

        int t000 = __ldg(btab + base);
        int t100 = t000; if (px) t100 = vx1 ? __ldg(btab + base + GG * GG) : -1;
        int t010 = t000; if (py) t010 = vy1 ? __ldg(btab + base + GG) : -1;
        int t001 = t000; if (pz) t001 = vz1 ? __ldg(btab + base + 1) : -1;
        int t110;
        if (px && py)      t110 = (vx1 && vy1) ? __ldg(btab + base + GG * GG + GG) : -1;
        else if (px)       t110 = t100;
        else               t110 = t010;
        int t101;
        if (px && pz)      t101 = (vx1 && vz1) ? __ldg(btab + base + GG * GG + 1) : -1;
        else if (px)       t101 = t100;
        else               t101 = t001;
        int t011;
        if (py && pz)      t011 = (vy1 && vz1) ? __ldg(btab + base + GG + 1) : -1;
        else if (py)       t011 = t010;
        else               t011 = t001;
        int t111;
        if (!pz)           t111 = t110;
        else if (!py)      t111 = t101;
        else if (!px)      t111 = t011;
        else               t111 = (vx1 && vy1 && vz1) ? __ldg(btab + base + GG * GG + GG + 1) : -1;

        int tb[8] = {t000, t001, t010, t011, t100, t101, t110, t111};

        bool ok = true;
        int foff[8];
        int lx0 = xi & 7, lx1 = (xi + 1) & 7;
        int ly0 = yi & 7, ly1 = (yi + 1) & 7;
        int lz0 = zi & 7, lz1 = (zi + 1) & 7;
        #pragma unroll
        for (int c = 0; c < 8; c++) {
            int b = tb[c];
            ok = ok && (b >= 0);
            int bs = b < 0 ? 0 : b;
            int lx = (c & 4) ? lx1 : lx0;
            int ly = (c & 2) ? ly1 : ly0;
            int lz = (c & 1) ? lz1 : lz0;
            foff[c] = bs * (STRIDE_V * NF) + ((lx * 8 + ly) * 8 + lz) * NF;
        }
        m = ok ? 1.0f : 0.0f;

        // ~48% of points have a missing corner block: skip their gathers entirely.
        if (ok) {
            float wx1 = frx, wx0 = 1.0f - frx;
            float wy1 = fry, wy0 = 1.0f - fry;
            float wz1 = frz, wz0 = 1.0f - frz;

            // ---- gather: 2x LDG.128 per corner (20B span always inside 32B window) ----
            #pragma unroll
            for (int h = 0; h < 2; h++) {
                float4 A[4], B[4];
                int sh[4];
                #pragma unroll
                for (int q = 0; q < 4; q++) {
                    int fo = foff[h * 4 + q];
                    sh[q] = fo & 3;
                    const float4* p = reinterpret_cast<const float4*>(feat + (fo & ~3));
                    A[q] = __ldg(p);
                    B[q] = __ldg(p + 1);
                }
                #pragma unroll
                for (int q = 0; q < 4; q++) {
                    int c = h * 4 + q;
                    bool s1 = (sh[q] & 1) != 0;
                    bool s2 = (sh[q] & 2) != 0;
                    float e0 = A[q].x, e1 = A[q].y, e2 = A[q].z, e3 = A[q].w;
                    float e4 = B[q].x, e5 = B[q].y, e6 = B[q].z, e7 = B[q].w;
                    float v0 = s2 ? (s1 ? e3 : e2) : (s1 ? e1 : e0);
                    float v1 = s2 ? (s1 ? e4 : e3) : (s1 ? e2 : e1);
                    float v2 = s2 ? (s1 ? e5 : e4) : (s1 ? e3 : e2);
                    float v3 = s2 ? (s1 ? e6 : e5) : (s1 ? e4 : e3);
                    float v4 = s2 ? (s1 ? e7 : e6) : (s1 ? e5 : e4);

                    float wx = (c & 4) ? wx1 : wx0;
                    float wy = (c & 2) ? wy1 : wy0;
                    float wz = (c & 1) ? wz1 : wz0;
                    float sx = (c & 4) ? 1.0f : -1.0f;
                    float sy = (c & 2) ? 1.0f : -1.0f;
                    float sz = (c & 1) ? 1.0f : -1.0f;
                    float w   = wx * wy * wz;
                    float dwx = sx * wy * wz;
                    float dwy = wx * sy * wz;
                    float dwz = wx * wy * sz;

                    float vv[NF] = {v0, v1, v2, v3, v4};
                    #pragma unroll
                    for (int f = 0; f < NF; f++) {
                        float t = vv[f];
                        acc[f]     = fmaf(w,   t, acc[f]);
                        accd[f][0] = fmaf(dwx, t, accd[f][0]);
                        accd[f][1] = fmaf(dwy, t, accd[f][1]);
                        accd[f][2] = fmaf(dwz, t, accd[f][2]);
                    }
                }
            }
        }
    }

    // ---- stage per-thread outputs in smem ----
    #pragma unroll
    for (int f = 0; f < NF; f++) s_feats[tid * NF + f] = acc[f] * m;
    float md = m * INV_V;
    #pragma unroll
    for (int f = 0; f < NF; f++) {
        s_dfx[tid * (NF * 3) + f * 3 + 0] = accd[f][0] * md;
        s_dfx[tid * (NF * 3) + f * 3 + 1] = accd[f][1] * md;
        s_dfx[tid * (NF * 3) + f * 3 + 2] = accd[f][2] * md;
    }
    s_mask[tid] = m;
    __syncthreads();

    // ---- coalesced streaming stores (write-through, don't pollute L2) ----
    {
        int cnt = rem * NF;
        float* g = out + (size_t)blk * TPB * NF;
        const float4* s4 = (const float4*)s_feats;
        float4* g4 = (float4*)g;
        int n4 = cnt >> 2;
        for (int idx = tid; idx < n4; idx += TPB) __stwt(&g4[idx], s4[idx]);
        for (int idx = (n4 << 2) + tid; idx < cnt; idx += TPB) __stwt(&g[idx], s_feats[idx]);
    }
    {
        int cnt = rem * NF * 3;
        float* g = out + (size_t)n * NF + (size_t)blk * TPB * NF * 3;
        const float4* s4 = (const float4*)s_dfx;
        float4* g4 = (float4*)g;
        int n4 = cnt >> 2;
        for (int idx = tid; idx < n4; idx += TPB) __stwt(&g4[idx], s4[idx]);
        for (int idx = (n4 << 2) + tid; idx < cnt; idx += TPB) __stwt(&g[idx], s_dfx[idx]);
    }
    {
        int cnt = rem;
        float* g = out + (size_t)n * NF * 4 + (size_t)blk * TPB;
        const float4* s4 = (const float4*)s_mask;
        float4* g4 = (float4*)g;
        int n4 = cnt >> 2;
        for (int idx = tid; idx < n4; idx += TPB) __stwt(&g4[idx], s4[idx]);
        for (int idx = (n4 << 2) + tid; idx < cnt; idx += TPB) __stwt(&g[idx], s_mask[idx]);
    }
}

extern "C" void kernel_launch(void* const* d_in, const int* in_sizes, int n_in,
                              void* d_out, int out_size)
{
    const float* x    = (const float*)d_in[0];
    const float* feat = (const float*)d_in[1];
    const int*   btab = (const int*)d_in[2];
    float* out = (float*)d_out;

    int n = in_sizes[0] / 3;
    int blocks = (n + TPB - 1) / TPB;
    hashgrid_kernel<<<blocks, TPB>>>(x, feat, btab, out, n);
}

// round 11
// speedup vs baseline: 2.1076x; 1.0170x over previous
#include <cuda_runtime.h>
#include <cuda_bf16.h>

#define NF 5
#define GG 32
#define STRIDE_V 520
#define TPB 256

// XLA folds x / 0.01f into x * fl(1/fl(0.01f)) == x * 100.0f exactly.
#define INV_V 100.0f

__global__ __launch_bounds__(TPB) void hashgrid_kernel(
    const float* __restrict__ x,
    const float* __restrict__ feat,
    const int*   __restrict__ btab,
    float* __restrict__ out,
    int n)
{
    __shared__ __align__(16) float s_feats[TPB * NF];
    __shared__ __align__(16) float s_dfx[TPB * NF * 3];
    __shared__ __align__(16) float s_mask[TPB];

    const int tid = threadIdx.x;
    const int blk = blockIdx.x;
    const int i = blk * TPB + tid;
    int rem = n - blk * TPB;
    if (rem > TPB) rem = TPB;

    float acc[NF] = {0.f, 0.f, 0.f, 0.f, 0.f};
    float accd[NF][3];
    #pragma unroll
    for (int f = 0; f < NF; f++) { accd[f][0] = 0.f; accd[f][1] = 0.f; accd[f][2] = 0.f; }
    float m = 0.0f;

    if (i < n) {
        // x is read exactly once -> evict-first, keep L2 for the feat table.
        float ux = __ldcs(x + 3 * i + 0) * INV_V;
        float uy = __ldcs(x + 3 * i + 1) * INV_V;
        float uz = __ldcs(x + 3 * i + 2) * INV_V;

        float fx = floorf(ux), fy = floorf(uy), fz = floorf(uz);
        int xi = (int)fx, yi = (int)fy, zi = (int)fz;
        float frx = ux - fx, fry = uy - fy, frz = uz - fz;

        // ---- block-table lookups with dedup (corners share blocks unless on a face) ----
        int bx0 = xi >> 3, bx1 = (xi + 1) >> 3;
        int by0 = yi >> 3, by1 = (yi + 1) >> 3;
        int bz0 = zi >> 3, bz1 = (zi + 1) >> 3;
        bool px = (bx1 != bx0), py = (by1 != by0), pz = (bz1 != bz0);
        bool vx1 = (bx1 < GG), vy1 = (by1 < GG), vz1 = (bz1 < GG);
        int base = (bx0 * GG + by0) * GG + bz0;

        int t000 = __ldg(btab + base);
        int t100 = t000; if (px) t100 = vx1 ? __ldg(btab + base + GG * GG) : -1;
        int t010 = t000; if (py) t010 = vy1 ? __ldg(btab + base + GG) : -1;
        int t001 = t000; if (pz) t001 = vz1 ? __ldg(btab + base + 1) : -1;
        int t110;
        if (px && py)      t110 = (vx1 && vy1) ? __ldg(btab + base + GG * GG + GG) : -1;
        else if (px)       t110 = t100;
        else               t110 = t010;
        int t101;
        if (px && pz)      t101 = (vx1 && vz1) ? __ldg(btab + base + GG * GG + 1) : -1;
        else if (px)       t101 = t100;
        else               t101 = t001;
        int t011;
        if (py && pz)      t011 = (vy1 && vz1) ? __ldg(btab + base + GG + 1) : -1;
        else if (py)       t011 = t010;
        else               t011 = t001;
        int t111;
        if (!pz)           t111 = t110;
        else if (!py)      t111 = t101;
        else if (!px)      t111 = t011;
        else               t111 = (vx1 && vy1 && vz1) ? __ldg(btab + base + GG * GG + GG + 1) : -1;

        int tb[8] = {t000, t001, t010, t011, t100, t101, t110, t111};

        bool ok = true;
        int foff[8];
        int lx0 = xi & 7, lx1 = (xi + 1) & 7;
        int ly0 = yi & 7, ly1 = (yi + 1) & 7;
        int lz0 = zi & 7, lz1 = (zi + 1) & 7;
        #pragma unroll
        for (int c = 0; c < 8; c++) {
            int b = tb[c];
            ok = ok && (b >= 0);
            int bs = b < 0 ? 0 : b;
            int lx = (c & 4) ? lx1 : lx0;
            int ly = (c & 2) ? ly1 : ly0;
            int lz = (c & 1) ? lz1 : lz0;
            foff[c] = bs * (STRIDE_V * NF) + ((lx * 8 + ly) * 8 + lz) * NF;
        }
        m = ok ? 1.0f : 0.0f;

        // ~48% of points have a missing corner block: skip their gathers entirely.
        if (ok) {
            float wx1 = frx, wx0 = 1.0f - frx;
            float wy1 = fry, wy0 = 1.0f - fry;
            float wz1 = frz, wz0 = 1.0f - frz;

            // ---- gather: 2x LDG.128 per corner (20B span always inside 32B window) ----
            #pragma unroll
            for (int h = 0; h < 2; h++) {
                float4 A[4], B[4];
                int sh[4];
                #pragma unroll
                for (int q = 0; q < 4; q++) {
                    int fo = foff[h * 4 + q];
                    sh[q] = fo & 3;
                    const float4* p = reinterpret_cast<const float4*>(feat + (fo & ~3));
                    A[q] = __ldg(p);
                    B[q] = __ldg(p + 1);
                }
                #pragma unroll
                for (int q = 0; q < 4; q++) {
                    int c = h * 4 + q;
                    bool s1 = (sh[q] & 1) != 0;
                    bool s2 = (sh[q] & 2) != 0;
                    float e0 = A[q].x, e1 = A[q].y, e2 = A[q].z, e3 = A[q].w;
                    float e4 = B[q].x, e5 = B[q].y, e6 = B[q].z, e7 = B[q].w;
                    float v0 = s2 ? (s1 ? e3 : e2) : (s1 ? e1 : e0);
                    float v1 = s2 ? (s1 ? e4 : e3) : (s1 ? e2 : e1);
                    float v2 = s2 ? (s1 ? e5 : e4) : (s1 ? e3 : e2);
                    float v3 = s2 ? (s1 ? e6 : e5) : (s1 ? e4 : e3);
                    float v4 = s2 ? (s1 ? e7 : e6) : (s1 ? e5 : e4);

                    float wx = (c & 4) ? wx1 : wx0;
                    float wy = (c & 2) ? wy1 : wy0;
                    float wz = (c & 1) ? wz1 : wz0;
                    float sx = (c & 4) ? 1.0f : -1.0f;
                    float sy = (c & 2) ? 1.0f : -1.0f;
                    float sz = (c & 1) ? 1.0f : -1.0f;
                    float w   = wx * wy * wz;
                    float dwx = sx * wy * wz;
                    float dwy = wx * sy * wz;
                    float dwz = wx * wy * sz;

                    float vv[NF] = {v0, v1, v2, v3, v4};
                    #pragma unroll
                    for (int f = 0; f < NF; f++) {
                        float t = vv[f];
                        acc[f]     = fmaf(w,   t, acc[f]);
                        accd[f][0] = fmaf(dwx, t, accd[f][0]);
                        accd[f][1] = fmaf(dwy, t, accd[f][1]);
                        accd[f][2] = fmaf(dwz, t, accd[f][2]);
                    }
                }
            }
        }
    }

    // ---- stage per-thread outputs in smem ----
    #pragma unroll
    for (int f = 0; f < NF; f++) s_feats[tid * NF + f] = acc[f] * m;
    float md = m * INV_V;
    #pragma unroll
    for (int f = 0; f < NF; f++) {
        s_dfx[tid * (NF * 3) + f * 3 + 0] = accd[f][0] * md;
        s_dfx[tid * (NF * 3) + f * 3 + 1] = accd[f][1] * md;
        s_dfx[tid * (NF * 3) + f * 3 + 2] = accd[f][2] * md;
    }
    s_mask[tid] = m;
    __syncthreads();

    // ---- coalesced streaming stores (write-through, don't pollute L2) ----
    {
        int cnt = rem * NF;
        float* g = out + (size_t)blk * TPB * NF;
        const float4* s4 = (const float4*)s_feats;
        float4* g4 = (float4*)g;
        int n4 = cnt >> 2;
        for (int idx = tid; idx < n4; idx += TPB) __stwt(&g4[idx], s4[idx]);
        for (int idx = (n4 << 2) + tid; idx < cnt; idx += TPB) __stwt(&g[idx], s_feats[idx]);
    }
    {
        int cnt = rem * NF * 3;
        float* g = out + (size_t)n * NF + (size_t)blk * TPB * NF * 3;
        const float4* s4 = (const float4*)s_dfx;
        float4* g4 = (float4*)g;
        int n4 = cnt >> 2;
        for (int idx = tid; idx < n4; idx += TPB) __stwt(&g4[idx], s4[idx]);
        for (int idx = (n4 << 2) + tid; idx < cnt; idx += TPB) __stwt(&g[idx], s_dfx[idx]);
    }
    {
        int cnt = rem;
        float* g = out + (size_t)n * NF * 4 + (size_t)blk * TPB;
        const float4* s4 = (const float4*)s_mask;
        float4* g4 = (float4*)g;
        int n4 = cnt >> 2;
        for (int idx = tid; idx < n4; idx += TPB) __stwt(&g4[idx], s4[idx]);
        for (int idx = (n4 << 2) + tid; idx < cnt; idx += TPB) __stwt(&g[idx], s_mask[idx]);
    }
}

extern "C" void kernel_launch(void* const* d_in, const int* in_sizes, int n_in,
                              void* d_out, int out_size)
{
    const float* x    = (const float*)d_in[0];
    const float* feat = (const float*)d_in[1];
    const int*   btab = (const int*)d_in[2];
    float* out = (float*)d_out;

    int n = in_sizes[0] / 3;
    int blocks = (n + TPB - 1) / TPB;
    hashgrid_kernel<<<blocks, TPB>>>(x, feat, btab, out, n);
}